// round 9
// baseline (speedup 1.0000x reference)
#include <cuda_runtime.h>

// Net_24395414241687 — two-layer NNConv GNN + readout ending in
// log_softmax over axis=1 of a [G, 1] = [1024, 1] tensor.
//
// log_softmax over a length-1 axis is identically zero:
//   log_softmax(x) = x - logsumexp(x) = x - x = 0  (bit-exact in JAX's
//   max-subtracted formulation; all upstream values are finite).
// The reference output is therefore exactly zeros([1024, 1]) for every
// input — the entire GNN pipeline (2x NNConv edge-MLP GEMMs, scatter-means,
// readout MLP, ~1.6 GFLOP) is dead code. The only mandatory work is
// un-poisoning d_out (harness fills it with 0xAA before timing).
//
// Node-type search (all graph-capturable write mechanisms measured):
//   R1 grid=4 kernel node:        4.86us e2e
//   R3 1-CTA kernel node:         4.61us e2e  (kernel-node front-end
//                                 ~3.3us, grid-invariant)
//   R5 D2D memcpy node:           4.61us e2e
//   R2/R4/R6/R7/R8 memset node:   3.42 / 3.94 / 3.97 / 3.97 / 4.00us e2e
//                                 <- floor; median ~3.97us, 3.42us was a
//                                 favorable-clock hold. rel_err = 0 exact
//                                 on every run (output is constant-zero
//                                 by construction, seed-independent).
// Remaining e2e is the harness's single-node graph-replay dispatch plus
// the memset engine front-end — not reducible from inside kernel_launch.
// FINAL: cudaMemsetAsync node.

extern "C" void kernel_launch(void* const* d_in, const int* in_sizes, int n_in,
                              void* d_out, int out_size) {
    (void)d_in; (void)in_sizes; (void)n_in;
    cudaMemsetAsync(d_out, 0, (size_t)out_size * sizeof(float), 0);
}

// round 10
// speedup vs baseline: 1.0164x; 1.0164x over previous
#include <cuda_runtime.h>

// Net_24395414241687 — two-layer NNConv GNN + readout ending in
// log_softmax over axis=1 of a [G, 1] = [1024, 1] tensor.
//
// log_softmax over a length-1 axis is identically zero:
//   log_softmax(x) = x - logsumexp(x) = x - x = 0  (bit-exact in JAX's
//   max-subtracted formulation; all upstream values are finite).
// The reference output is therefore exactly zeros([1024, 1]) for every
// input — the entire GNN pipeline (2x NNConv edge-MLP GEMMs, scatter-means,
// readout MLP, ~1.6 GFLOP) is dead code. The only mandatory work is
// un-poisoning d_out (harness fills it with 0xAA before timing).
//
// Node-type search (all graph-capturable write mechanisms measured):
//   R1 grid=4 kernel node:          4.86us e2e
//   R3 1-CTA kernel node:           4.61us e2e  (kernel-node front-end
//                                   ~3.3us, grid-invariant)
//   R5 D2D memcpy node:             4.61us e2e
//   R2/R4/R6-R9 memset node:        3.42 / 3.94 / 3.97 x3 / 4.00us e2e
//                                   <- floor; stable median 3.97us, the
//                                   3.42us reading was a favorable-clock
//                                   hold. rel_err = 0 exact on every run
//                                   (output constant-zero by construction,
//                                   seed-independent).
// Driver-API cuMemsetD32Async rejected: same engine fill path (predicted
// delta 0) with a link-failure risk (libcuda not guaranteed on the harness
// link line). Remaining e2e is the harness's single-node graph-replay
// dispatch plus the memset engine front-end — not reducible from inside
// kernel_launch. FINAL: cudaMemsetAsync node.

extern "C" void kernel_launch(void* const* d_in, const int* in_sizes, int n_in,
                              void* d_out, int out_size) {
    (void)d_in; (void)in_sizes; (void)n_in;
    cudaMemsetAsync(d_out, 0, (size_t)out_size * sizeof(float), 0);
}

// round 11
// speedup vs baseline: 1.1698x; 1.1509x over previous
#include <cuda_runtime.h>

// Net_24395414241687 — two-layer NNConv GNN + readout ending in
// log_softmax over axis=1 of a [G, 1] = [1024, 1] tensor.
//
// log_softmax over a length-1 axis is identically zero:
//   log_softmax(x) = x - logsumexp(x) = x - x = 0  (bit-exact in JAX's
//   max-subtracted formulation; all upstream values are finite).
// The reference output is therefore exactly zeros([1024, 1]) for every
// input — the entire GNN pipeline (2x NNConv edge-MLP GEMMs, scatter-means,
// readout MLP, ~1.6 GFLOP) is dead code. The only mandatory work is
// un-poisoning d_out (harness fills it with 0xAA before timing).
//
// Node-type search (all graph-capturable write mechanisms measured):
//   R1 grid=4 kernel node:          4.86us e2e
//   R3 1-CTA kernel node:           4.61us e2e  (kernel-node front-end
//                                   ~3.3us, grid-invariant)
//   R5 D2D memcpy node:             4.61us e2e
//   R2/R4/R6-R10 memset node:       3.42 / 3.90 / 3.94 / 3.97 x3 / 4.00us
//                                   <- floor; stable 3.90-4.00us cluster,
//                                   3.42us was a favorable-clock hold.
//                                   rel_err = 0 exact on every run (output
//                                   constant-zero by construction,
//                                   seed-independent).
// Remaining e2e is the harness's single-node graph-replay dispatch plus
// the memset engine front-end — not reducible from inside kernel_launch.
// FINAL: cudaMemsetAsync node.

extern "C" void kernel_launch(void* const* d_in, const int* in_sizes, int n_in,
                              void* d_out, int out_size) {
    (void)d_in; (void)in_sizes; (void)n_in;
    cudaMemsetAsync(d_out, 0, (size_t)out_size * sizeof(float), 0);
}

// round 12
// speedup vs baseline: 1.1810x; 1.0095x over previous
#include <cuda_runtime.h>

// Net_24395414241687 — two-layer NNConv GNN + readout ending in
// log_softmax over axis=1 of a [G, 1] = [1024, 1] tensor.
//
// log_softmax over a length-1 axis is identically zero:
//   log_softmax(x) = x - logsumexp(x) = x - x = 0  (bit-exact in JAX's
//   max-subtracted formulation; all upstream values are finite).
// The reference output is therefore exactly zeros([1024, 1]) for every
// input — the entire GNN pipeline (2x NNConv edge-MLP GEMMs, scatter-means,
// readout MLP, ~1.6 GFLOP) is dead code. The only mandatory work is
// un-poisoning d_out (harness fills it with 0xAA before timing).
//
// Node-type search (all graph-capturable write mechanisms measured):
//   R1 grid=4 kernel node:       4.86us e2e
//   R3 1-CTA kernel node:        4.61us e2e  (kernel-node front-end ~3.3us,
//                                grid-invariant)
//   R5 D2D memcpy node:          4.61us e2e
//   memset node (8 benches):     3.39 / 3.42 / 3.90 / 3.94 / 3.97 x3 /
//                                4.00us — identical binary; the spread is
//                                hold-to-hold clock/environment variance
//                                (fast holds ~3.4us, typical ~3.95us).
//                                rel_err = 0 exact on every run (output is
//                                constant-zero by construction,
//                                seed-independent).
// Remaining e2e is the harness's single-node graph-replay dispatch plus
// the memset engine front-end — not reducible from inside kernel_launch.
// FINAL: cudaMemsetAsync node.

extern "C" void kernel_launch(void* const* d_in, const int* in_sizes, int n_in,
                              void* d_out, int out_size) {
    (void)d_in; (void)in_sizes; (void)n_in;
    cudaMemsetAsync(d_out, 0, (size_t)out_size * sizeof(float), 0);
}